// round 1
// baseline (speedup 1.0000x reference)
#include <cuda_runtime.h>

#define B_ 2048
#define T_ 500
#define N_ 64

// Rowsum scratch, stored [T][B] so the scan kernel reads coalesced.
// Padded by 8 rows so the scan's prefetch can read past t=T-1 unguarded.
__device__ float g_S[(T_ + 8) * B_];

// ---------------------------------------------------------------------------
// Kernel 1: S[t*B + b] = sum_n input[b][t][n]
// One warp per (b,t) row; each lane loads a float2 (64 floats / 32 lanes),
// so the warp reads a fully-coalesced 256B chunk. DRAM-bound by design.
// ---------------------------------------------------------------------------
__global__ void rowsum_kernel(const float* __restrict__ in) {
    unsigned wid  = (blockIdx.x * blockDim.x + threadIdx.x) >> 5;
    unsigned lane = threadIdx.x & 31;
    if (wid >= (unsigned)(B_ * T_)) return;

    const float2* p = reinterpret_cast<const float2*>(in) + (size_t)wid * 32u + lane;
    float2 x = *p;
    float v = x.x + x.y;
    #pragma unroll
    for (int o = 16; o; o >>= 1)
        v += __shfl_xor_sync(0xffffffffu, v, o);

    if (lane == 0) {
        unsigned b = wid / T_;
        unsigned t = wid - b * T_;
        g_S[t * B_ + b] = v;
    }
}

// ---------------------------------------------------------------------------
// Izhikevich Euler step (DT = 0.25, V_TH = 30). Mutates v,u; returns spike 0/1.
// Kept close to reference association; reset clamps kill drift.
// ---------------------------------------------------------------------------
__device__ __forceinline__ float izh(float& v, float& u, float I,
                                     float a, float b, float c, float d) {
    float s  = 0.04f * v * v + 5.0f * v + 140.0f - u + I;
    float vn = fmaf(0.25f, s, v);
    float un = fmaf(0.25f * a, fmaf(b, v, -u), u);
    bool  z  = (vn >= 30.0f);
    v = z ? c : vn;
    u = z ? (un + d) : un;
    return z ? 1.0f : 0.0f;
}

// ---------------------------------------------------------------------------
// Kernel 2: the T=500 sequential scan.
// 64 blocks x 64 threads. Warp 0 of a block = channel 1 for batches
// [b0, b0+32); warp 1 = channel 2 for the same batches. Channels share no
// state, so this doubles scan parallelism and halves per-thread work.
// S is prefetched in groups of 4 timesteps (double buffered) so L2 latency
// stays off the serial dependency chain.
//
// Output layout (floats), total 12*B*T:
//   [0      , BT)   o_spikes  = z6   (ch1 M spike)
//   [BT     , 2BT)  v         = vM
//   [2BT    , 3BT)  o_spikes2 = z62  (ch2)
//   [3BT    , 4BT)  v2        = vM2
//   [4BT    , 8BT)  o_spikes_o[B,T,4] = {z2,z3,z4,z5}
//   [8BT    ,12BT)  v_o       [B,T,4] = {vL,vE,vI,vT}
// ---------------------------------------------------------------------------
__global__ void __launch_bounds__(64, 1)
scan_kernel(const float* __restrict__ w, float* __restrict__ out) {
    const int lane = threadIdx.x & 31;
    const int ch   = threadIdx.x >> 5;           // 0 = channel 1, 1 = channel 2
    const int b    = blockIdx.x * 32 + lane;

    // Fold weight products into per-neuron input coefficients.
    float CL, CE, WE, WI, CT, WM;
    if (ch == 0) {
        CL = w[2] * (w[0] * w[1]);   // L drive:  w2*(zp*w1), zp = w0*S
        CE = w[0] * w[4];            // E drive:  zp*w4
        WE = w[5];                   // + z2*w5
        WI = w[6];                   // I drive:  z3*w6
        CT = w[9] * w[8];            // T drive:  w9*(z3*w8)
        WM = w[11];                  // M drive:  z5*w11
    } else {
        CL = w[2] * (w[12] * w[13]);
        CE = w[12] * w[16];
        WE = w[17];
        WI = w[18];
        CT = w[9] * w[20];
        WM = w[23];
    }
    const float W3  = w[3];          // LLBN self-feedback weight (both channels)
    const float W10 = w[10];         // TN self-feedback weight (both channels)

    // Initial states (identical for both channels).
    float vL = -70.f, uL = -14.f, zL = 0.f;       // LLBN  (a=.02,b=.20,c=-65,d=6)
    float vE = -64.f, uE = -16.f;                 // EBN   (a=.02,b=.25,c=-55,d=.05)
    float vI = -64.f, uI = -16.f;                 // IFN   (a=.02,b=.25,c=-65,d=6)
    float vT = -70.f, uT = -14.f, zT = 0.f;       // TN    (a=.02,b=.20,c=-50,d=2)
    float vM = -64.f, uM = -16.f;                 // MN = IFN

    const size_t BT = (size_t)B_ * T_;
    float* out_sA = out + (ch ? 2 * BT : 0)      + (size_t)b * T_;  // z6  / z62
    float* out_sB = out + (ch ? 3 * BT : 1 * BT) + (size_t)b * T_;  // vM  / vM2
    float4* out_o4 = reinterpret_cast<float4*>(out + 4 * BT) + (size_t)b * T_;
    float4* out_v4 = reinterpret_cast<float4*>(out + 8 * BT) + (size_t)b * T_;

    // S prefetch double-buffer: groups of 4 timesteps.
    float cur[4], nxt[4];
    #pragma unroll
    for (int j = 0; j < 4; j++) cur[j] = g_S[j * B_ + b];

    for (int t4 = 0; t4 < T_; t4 += 4) {
        #pragma unroll
        for (int j = 0; j < 4; j++) nxt[j] = g_S[(t4 + 4 + j) * B_ + b];

        float z6s[4], vMs[4];
        #pragma unroll
        for (int j = 0; j < 4; j++) {
            const float S = cur[j];

            // LLBN (self-feedback uses previous step's z2)
            float I  = fmaf(CL, S, W3 * zL);
            float z2 = izh(vL, uL, I, 0.02f, 0.20f, -65.f, 6.f);
            zL = z2;

            // EBN (uses fresh z2)
            I = fmaf(CE, S, WE * z2);
            float z3 = izh(vE, uE, I, 0.02f, 0.25f, -55.f, 0.05f);

            // IFN
            float z4 = izh(vI, uI, WI * z3, 0.02f, 0.25f, -65.f, 6.f);

            // TN (self-feedback uses previous step's z5)
            I = fmaf(CT, z3, W10 * zT);
            float z5 = izh(vT, uT, I, 0.02f, 0.20f, -50.f, 2.f);
            zT = z5;

            // MN
            float z6 = izh(vM, uM, WM * z5, 0.02f, 0.25f, -65.f, 6.f);

            z6s[j] = z6;
            vMs[j] = vM;

            if (ch == 0) {   // channel-1 warp also emits the 4-wide streams
                out_o4[t4 + j] = make_float4(z2, z3, z4, z5);
                out_v4[t4 + j] = make_float4(vL, vE, vI, vT);
            }
        }

        // Scalar streams: register-staged 4 steps -> one STG.128 each.
        *reinterpret_cast<float4*>(out_sA + t4) =
            make_float4(z6s[0], z6s[1], z6s[2], z6s[3]);
        *reinterpret_cast<float4*>(out_sB + t4) =
            make_float4(vMs[0], vMs[1], vMs[2], vMs[3]);

        #pragma unroll
        for (int j = 0; j < 4; j++) cur[j] = nxt[j];
    }
}

// ---------------------------------------------------------------------------
extern "C" void kernel_launch(void* const* d_in, const int* in_sizes, int n_in,
                              void* d_out, int out_size) {
    const float* inp = (const float*)d_in[0];
    const float* w   = (const float*)d_in[1];
    if (in_sizes[0] == 24) { const float* t = inp; inp = w; w = t; }

    // Kernel 1: B*T = 1,024,000 rows, 8 rows (warps) per 256-thread block.
    rowsum_kernel<<<(B_ * T_) / 8, 256>>>(inp);

    // Kernel 2: 2048 batches x 2 channels = 4096 threads.
    scan_kernel<<<64, 64>>>(w, (float*)d_out);
}